// round 1
// baseline (speedup 1.0000x reference)
#include <cuda_runtime.h>
#include <cuda_bf16.h>
#include <math.h>

#define NN 50000
#define NE 800000
#define EP (NE + NN)   // edges + self loops
#define FD 128

typedef unsigned long long ull;

// -------------------- device scratch (no allocs allowed) --------------------
__device__ float g_Q[NN * FD];
__device__ float g_K[NN * FD];
__device__ float g_V[NN * FD];
__device__ int   g_cnt[NN];
__device__ int   g_off[NN + 1];
__device__ int   g_cur[NN];
__device__ int   g_scol[EP];

// -------------------- packed f32x2 helpers --------------------
__device__ __forceinline__ ull pack2(float lo, float hi) {
    ull r; asm("mov.b64 %0, {%1, %2};" : "=l"(r) : "f"(lo), "f"(hi)); return r;
}
__device__ __forceinline__ ull ffma2(ull a, ull b, ull c) {
    ull d; asm("fma.rn.f32x2 %0, %1, %2, %3;" : "=l"(d) : "l"(a), "l"(b), "l"(c)); return d;
}
__device__ __forceinline__ float2 unpack2(ull v) {
    float2 r; asm("mov.b64 {%0, %1}, %2;" : "=f"(r.x), "=f"(r.y) : "l"(v)); return r;
}

// -------------------- GEMM: C = x @ W (+bias, relu optional) --------------------
// blockIdx.y: 0 -> Q (relu, qbias), 1 -> K (relu, kbias), 2 -> V (no bias, no relu)
// BM=64 rows, BN=128 cols, BK=8, 256 threads. Each thread: 8 rows x 4 cols, FFMA2.
__global__ __launch_bounds__(256) void gemm_qkv_kernel(
    const float* __restrict__ x,
    const float* __restrict__ Wq, const float* __restrict__ bq,
    const float* __restrict__ Wk, const float* __restrict__ bk,
    const float* __restrict__ Wv)
{
    const int mat = blockIdx.y;
    const float* __restrict__ W = (mat == 0) ? Wq : ((mat == 1) ? Wk : Wv);
    const float* __restrict__ B = (mat == 0) ? bq : ((mat == 1) ? bk : nullptr);
    float* __restrict__ C = (mat == 0) ? g_Q : ((mat == 1) ? g_K : g_V);
    const bool dorelu = (mat < 2);

    __shared__ float xs[8][64];    // [k][row]
    __shared__ float ws[8][128];   // [k][col]

    const int t   = threadIdx.x;
    const int tx  = t & 31;        // col group (4 cols each)
    const int ty  = t >> 5;        // row group (8 rows each); constant per warp
    const int row0 = blockIdx.x * 64;

    ull acc[8][2];
#pragma unroll
    for (int i = 0; i < 8; i++) { acc[i][0] = 0ull; acc[i][1] = 0ull; }

    for (int k0 = 0; k0 < FD; k0 += 8) {
        // load x tile: 64 rows x 8 k
        {
            int r  = t >> 2;
            int kk = (t & 3) * 2;
            float2 v = make_float2(0.f, 0.f);
            if (row0 + r < NN)
                v = *(const float2*)(x + (size_t)(row0 + r) * FD + k0 + kk);
            xs[kk][r]     = v.x;
            xs[kk + 1][r] = v.y;
        }
        // load W tile: 8 k x 128 cols
        {
            int kk = t >> 5;
            int n4 = (t & 31) * 4;
            float4 w = *(const float4*)(W + (size_t)(k0 + kk) * FD + n4);
            *(float4*)&ws[kk][n4] = w;
        }
        __syncthreads();

#pragma unroll
        for (int kk = 0; kk < 8; kk++) {
            float4 xa = *(const float4*)&xs[kk][ty * 8];
            float4 xb = *(const float4*)&xs[kk][ty * 8 + 4];
            float4 w  = *(const float4*)&ws[kk][tx * 4];
            ull w01 = pack2(w.x, w.y);
            ull w23 = pack2(w.z, w.w);
            float xr[8] = {xa.x, xa.y, xa.z, xa.w, xb.x, xb.y, xb.z, xb.w};
#pragma unroll
            for (int i = 0; i < 8; i++) {
                ull xi = pack2(xr[i], xr[i]);
                acc[i][0] = ffma2(xi, w01, acc[i][0]);
                acc[i][1] = ffma2(xi, w23, acc[i][1]);
            }
        }
        __syncthreads();
    }

    float4 bv = make_float4(0.f, 0.f, 0.f, 0.f);
    if (B) bv = *(const float4*)(B + tx * 4);

#pragma unroll
    for (int i = 0; i < 8; i++) {
        int r = row0 + ty * 8 + i;
        if (r < NN) {
            float2 a0 = unpack2(acc[i][0]);
            float2 a1 = unpack2(acc[i][1]);
            float4 o = make_float4(a0.x + bv.x, a0.y + bv.y, a1.x + bv.z, a1.y + bv.w);
            if (dorelu) {
                o.x = fmaxf(o.x, 0.f); o.y = fmaxf(o.y, 0.f);
                o.z = fmaxf(o.z, 0.f); o.w = fmaxf(o.w, 0.f);
            }
            *(float4*)(C + (size_t)r * FD + tx * 4) = o;
        }
    }
}

// -------------------- counting sort of edges by target node --------------------
__global__ void init_cnt_kernel() {
    int i = blockIdx.x * blockDim.x + threadIdx.x;
    if (i < NN) g_cnt[i] = 1;   // self loop pre-counted
}

__global__ void hist_kernel(const int* __restrict__ ei) {
    int e = blockIdx.x * blockDim.x + threadIdx.x;
    if (e < NE) atomicAdd(&g_cnt[ei[e]], 1);   // row = target = ei[0][e]
}

// single-block exclusive scan over g_cnt -> g_off (and g_cur copy)
__global__ __launch_bounds__(1024) void scan_kernel() {
    __shared__ int sums[1024];
    const int t = threadIdx.x;
    const int CH = (NN + 1023) / 1024;   // 49
    int start = t * CH;
    int end   = start + CH; if (end > NN) end = NN;

    int s = 0;
    for (int i = start; i < end; i++) s += g_cnt[i];
    sums[t] = s;
    __syncthreads();
    for (int d = 1; d < 1024; d <<= 1) {
        int v = (t >= d) ? sums[t - d] : 0;
        __syncthreads();
        sums[t] += v;
        __syncthreads();
    }
    int run = sums[t] - s;   // exclusive prefix for this thread's chunk
    for (int i = start; i < end; i++) {
        g_off[i] = run;
        g_cur[i] = run;
        run += g_cnt[i];
    }
    if (start < NN && end == NN) g_off[NN] = run;
}

__global__ void scatter_kernel(const int* __restrict__ ei) {
    int e = blockIdx.x * blockDim.x + threadIdx.x;
    if (e >= EP) return;
    int r, c;
    if (e < NE) { r = ei[e]; c = ei[NE + e]; }
    else        { r = e - NE; c = r; }          // self loop
    int pos = atomicAdd(&g_cur[r], 1);
    g_scol[pos] = c;
}

// -------------------- fused attention + aggregation --------------------
// One warp per target node. Online softmax over its edge list.
// lane l owns output dims [4l, 4l+4) -> all within head (l>>2); shfl over the
// 4-lane group reduces the per-head 16-dim dot product.
__global__ __launch_bounds__(256) void aggregate_kernel(
    const float* __restrict__ bias, float* __restrict__ out)
{
    const int warp = (blockIdx.x * blockDim.x + threadIdx.x) >> 5;
    const int lane = threadIdx.x & 31;
    if (warp >= NN) return;
    const int n = warp;

    const float4 q = *(const float4*)(g_Q + (size_t)n * FD + lane * 4);

    int beg = g_off[n];
    int end = g_off[n + 1];

    float m = -INFINITY;
    float s = 0.f;
    float4 acc = make_float4(0.f, 0.f, 0.f, 0.f);

    int c = (beg < end) ? g_scol[beg] : 0;
    for (int e = beg; e < end; e++) {
        int cn = (e + 1 < end) ? g_scol[e + 1] : 0;   // prefetch next col idx
        const float4 k4 = *(const float4*)(g_K + (size_t)c * FD + lane * 4);
        const float4 v4 = *(const float4*)(g_V + (size_t)c * FD + lane * 4);

        float tsc = q.x * k4.x + q.y * k4.y + q.z * k4.z + q.w * k4.w;
        tsc += __shfl_xor_sync(0xffffffffu, tsc, 1);
        tsc += __shfl_xor_sync(0xffffffffu, tsc, 2);   // per-head score

        float nm = fmaxf(m, tsc);
        float f  = __expf(m - nm);    // first iter: exp(-inf) = 0
        float w  = __expf(tsc - nm);
        s = s * f + w;
        acc.x = acc.x * f + w * v4.x;
        acc.y = acc.y * f + w * v4.y;
        acc.z = acc.z * f + w * v4.z;
        acc.w = acc.w * f + w * v4.w;
        m = nm;
        c = cn;
    }

    const float inv = 1.f / s;
    const float4 b4 = *(const float4*)(bias + lane * 4);
    float4 o = make_float4(acc.x * inv + b4.x, acc.y * inv + b4.y,
                           acc.z * inv + b4.z, acc.w * inv + b4.w);
    *(float4*)(out + (size_t)n * FD + lane * 4) = o;
}

// -------------------- launch --------------------
extern "C" void kernel_launch(void* const* d_in, const int* in_sizes, int n_in,
                              void* d_out, int out_size)
{
    const float* x  = (const float*)d_in[0];
    const int*   ei = (const int*)d_in[1];
    const float* Wq = (const float*)d_in[2];
    const float* bq = (const float*)d_in[3];
    const float* Wk = (const float*)d_in[4];
    const float* bk = (const float*)d_in[5];
    const float* Wv = (const float*)d_in[6];
    const float* bo = (const float*)d_in[7];
    float* out = (float*)d_out;

    // edge sort chain
    init_cnt_kernel<<<(NN + 255) / 256, 256>>>();
    hist_kernel<<<(NE + 255) / 256, 256>>>(ei);
    scan_kernel<<<1, 1024>>>();
    scatter_kernel<<<(EP + 255) / 256, 256>>>(ei);

    // dense Q/K/V
    dim3 ggrid((NN + 63) / 64, 3);
    gemm_qkv_kernel<<<ggrid, 256>>>(x, Wq, bq, Wk, bk, Wv);

    // fused attention + aggregation (1 warp / node)
    aggregate_kernel<<<(NN * 32 + 255) / 256, 256>>>(bo, out);
}